// round 5
// baseline (speedup 1.0000x reference)
#include <cuda_runtime.h>
#include <cstdint>
#include <cstddef>

#define NMAX 50000
#define EMAX 800000
#define HDIM 128
#define NG 64
#define BN_EPS_F 1e-5f
#define SCAN_BLK 1024
#define MAXNB 64   // ceil(NMAX/SCAN_BLK) = 49

// ---------------- scratch (static device globals; no runtime alloc) ----------
__device__ int   g_is64;               // 1 if int inputs are int64, 0 if int32
__device__ int   g_deg[NMAX];
__device__ int   g_incl[NMAX];         // block-local inclusive scan temp
__device__ int   g_bsum[MAXNB];
__device__ int   g_boff[MAXNB];
__device__ int   g_rowptr[NMAX + 1];
__device__ int   g_cursor[NMAX];
__device__ int   g_col[EMAX];
__device__ float g_dinv[NMAX];
__device__ __align__(16) float g_y[(size_t)NMAX * HDIM];
__device__ __align__(16) float g_h[(size_t)NMAX * HDIM];
__device__ __align__(16) float g_pool[NG * HDIM];

// dtype-dispatched integer load
__device__ __forceinline__ int idx_at(const void* p, long long i, int is64) {
    if (is64) return (int)((const long long*)p)[i];
    return ((const int*)p)[i];
}

// packed fp32x2 helpers (sm_100+)
__device__ __forceinline__ unsigned long long pack_dup(float a) {
    unsigned long long r;
    asm("mov.b64 %0, {%1, %1};" : "=l"(r) : "f"(a));
    return r;
}
__device__ __forceinline__ void ffma2(unsigned long long& d,
                                      unsigned long long a,
                                      unsigned long long b) {
    asm("fma.rn.f32x2 %0, %1, %2, %3;" : "=l"(d) : "l"(a), "l"(b), "l"(d));
}

// ---------------- dtype probe: odd 32-bit words all zero <=> int64 ----------
__global__ void k_probe(const unsigned* __restrict__ w, int nwords) {
    int i = blockIdx.x * blockDim.x + threadIdx.x;
    int odd = i * 2 + 1;
    if (odd < nwords && w[odd] != 0) g_is64 = 0;
}

__global__ void k_zero_deg(int n) {
    int i = blockIdx.x * blockDim.x + threadIdx.x;
    if (i == 0) g_is64 = 1;
    if (i < n) g_deg[i] = 0;
}

__global__ void k_hist(const void* __restrict__ ei, int e) {
    int i = blockIdx.x * blockDim.x + threadIdx.x;
    if (i < e) {
        int is64 = g_is64;
        int d = idx_at(ei, (long long)e + i, is64);   // dst row
        atomicAdd(&g_deg[d], 1);
    }
}

// -------- phase 1: block-local inclusive scan of g_deg -> g_incl, g_bsum -----
__global__ void __launch_bounds__(SCAN_BLK)
k_scan1(int n) {
    __shared__ int wsum[32];
    const int t = threadIdx.x, lane = t & 31, wid = t >> 5;
    const int i = blockIdx.x * SCAN_BLK + t;
    int v = (i < n) ? g_deg[i] : 0;
    int s = v;
    #pragma unroll
    for (int o = 1; o < 32; o <<= 1) {
        int u = __shfl_up_sync(0xffffffffu, s, o);
        if (lane >= o) s += u;
    }
    if (lane == 31) wsum[wid] = s;
    __syncthreads();
    if (wid == 0) {
        int ws = wsum[lane];
        int sc = ws;
        #pragma unroll
        for (int o = 1; o < 32; o <<= 1) {
            int u = __shfl_up_sync(0xffffffffu, sc, o);
            if (lane >= o) sc += u;
        }
        wsum[lane] = sc - ws;   // exclusive warp offset
    }
    __syncthreads();
    s += wsum[wid];
    if (i < n) g_incl[i] = s;
    if (t == SCAN_BLK - 1) g_bsum[blockIdx.x] = s;
}

// -------- phase 2: exclusive scan of block sums (nb <= 64), total -> rowptr[n]
__global__ void k_scan2(int nb, int n) {
    __shared__ int w0tot;
    const int t = threadIdx.x, lane = t & 31, wid = t >> 5;
    int v = (t < nb) ? g_bsum[t] : 0;
    int s = v;
    #pragma unroll
    for (int o = 1; o < 32; o <<= 1) {
        int u = __shfl_up_sync(0xffffffffu, s, o);
        if (lane >= o) s += u;
    }
    if (wid == 0 && lane == 31) w0tot = s;
    __syncthreads();
    int incl = s + (wid ? w0tot : 0);
    if (t < nb) g_boff[t] = incl - v;
    if (t == nb - 1) g_rowptr[n] = incl;
}

// -------- phase 3: finalize rowptr/cursor/dinv --------------------------------
__global__ void k_scan3(int n) {
    int i = blockIdx.x * blockDim.x + threadIdx.x;
    if (i < n) {
        int v = g_deg[i];
        int excl = g_incl[i] - v + g_boff[i / SCAN_BLK];
        g_rowptr[i] = excl;
        g_cursor[i] = excl;
        g_dinv[i]   = rsqrtf((float)(v + 1));  // +1 self-loop
    }
}

__global__ void k_fill(const void* __restrict__ ei, int e) {
    int i = blockIdx.x * blockDim.x + threadIdx.x;
    if (i < e) {
        int is64 = g_is64;
        int s = idx_at(ei, i, is64);
        int d = idx_at(ei, (long long)e + i, is64);
        int p = atomicAdd(&g_cursor[d], 1);
        g_col[p] = s;
    }
}

// ---------------- dense GEMM: g_y[M,128] = rowscale(A, dinv) @ W[K,128] ------
// Register double-buffered across 16-wide k-chunks.
// SRC == 0: A comes from the kernel argument (external input x)
// SRC == 1: A is the internal buffer g_h
template <int SRC>
__global__ void __launch_bounds__(256, 2)
k_gemm(const float* __restrict__ Aarg, const float* __restrict__ W,
       int M, int K)
{
    __shared__ __align__(16) float As[16][HDIM + 8];
    __shared__ __align__(16) float Bs[16][HDIM];
    const int tid = threadIdx.x;
    const int tx = tid & 15, ty = tid >> 4;
    const int row0 = blockIdx.x * 128;

    const float* A = (SRC == 0) ? Aarg : g_h;

    // packed accumulators: acc2[i][j] holds cols (2j, 2j+1) for row i
    unsigned long long acc2[8][4];
    #pragma unroll
    for (int i = 0; i < 8; i++)
        #pragma unroll
        for (int j = 0; j < 4; j++) acc2[i][j] = 0ULL;

    const int a_row = tid >> 2;  // 0..63
    const int a_q   = tid & 3;   // 0..3
    const int b_k0  = tid >> 5;  // 0..7
    const int b_cq  = tid & 31;  // 0..31

    float dv[2] = {0.f, 0.f};
    {
        int r0 = row0 + a_row;
        int r1 = r0 + 64;
        if (r0 < M) dv[0] = g_dinv[r0];
        if (r1 < M) dv[1] = g_dinv[r1];
    }

    float4 pa[2], pb[2];

    // prologue: load chunk 0 into registers
    {
        #pragma unroll
        for (int rr = 0; rr < 2; rr++) {
            int row = row0 + a_row + rr * 64;
            pa[rr] = make_float4(0.f, 0.f, 0.f, 0.f);
            if (row < M)
                pa[rr] = *(const float4*)(A + (size_t)row * K + a_q * 4);
        }
        #pragma unroll
        for (int rr = 0; rr < 2; rr++)
            pb[rr] = *(const float4*)(W + (size_t)(b_k0 + rr * 8) * HDIM + b_cq * 4);
    }

    for (int k0 = 0; k0 < K; k0 += 16) {
        // store current chunk registers -> smem
        #pragma unroll
        for (int rr = 0; rr < 2; rr++) {
            float s = dv[rr];
            As[a_q * 4 + 0][a_row + rr * 64] = pa[rr].x * s;
            As[a_q * 4 + 1][a_row + rr * 64] = pa[rr].y * s;
            As[a_q * 4 + 2][a_row + rr * 64] = pa[rr].z * s;
            As[a_q * 4 + 3][a_row + rr * 64] = pa[rr].w * s;
        }
        #pragma unroll
        for (int rr = 0; rr < 2; rr++)
            *(float4*)&Bs[b_k0 + rr * 8][b_cq * 4] = pb[rr];
        __syncthreads();

        // issue next chunk's global loads (latency hidden under compute)
        if (k0 + 16 < K) {
            int kn = k0 + 16;
            #pragma unroll
            for (int rr = 0; rr < 2; rr++) {
                int row = row0 + a_row + rr * 64;
                float4 v = make_float4(0.f, 0.f, 0.f, 0.f);
                if (row < M)
                    v = *(const float4*)(A + (size_t)row * K + kn + a_q * 4);
                pa[rr] = v;
            }
            #pragma unroll
            for (int rr = 0; rr < 2; rr++)
                pb[rr] = *(const float4*)(W + (size_t)(kn + b_k0 + rr * 8) * HDIM + b_cq * 4);
        }

        #pragma unroll
        for (int kk = 0; kk < 16; kk++) {
            float4 a0 = *(const float4*)&As[kk][ty * 8];
            float4 a1 = *(const float4*)&As[kk][ty * 8 + 4];
            ulonglong2 b0 = *(const ulonglong2*)&Bs[kk][tx * 8];
            ulonglong2 b1 = *(const ulonglong2*)&Bs[kk][tx * 8 + 4];
            unsigned long long bb[4] = {b0.x, b0.y, b1.x, b1.y};
            float av[8] = {a0.x, a0.y, a0.z, a0.w, a1.x, a1.y, a1.z, a1.w};
            #pragma unroll
            for (int i = 0; i < 8; i++) {
                unsigned long long ad = pack_dup(av[i]);
                #pragma unroll
                for (int j = 0; j < 4; j++)
                    ffma2(acc2[i][j], ad, bb[j]);
            }
        }
        __syncthreads();
    }

    #pragma unroll
    for (int i = 0; i < 8; i++) {
        int row = row0 + ty * 8 + i;
        if (row < M) {
            ulonglong2 v0 = make_ulonglong2(acc2[i][0], acc2[i][1]);
            ulonglong2 v1 = make_ulonglong2(acc2[i][2], acc2[i][3]);
            *(ulonglong2*)(g_y + (size_t)row * HDIM + tx * 8)     = v0;
            *(ulonglong2*)(g_y + (size_t)row * HDIM + tx * 8 + 4) = v1;
        }
    }
}

// -------- aggregation (pull / CSR): g_h = BN/ReLU(dinv*segsum(g_y) + b) ------
__global__ void __launch_bounds__(256)
k_aggr(const float* __restrict__ bias,
       const float* __restrict__ bng, const float* __restrict__ bnb,
       const float* __restrict__ bnm, const float* __restrict__ bnv,
       int do_bn, int n)
{
    int w = (blockIdx.x * blockDim.x + threadIdx.x) >> 5;
    if (w >= n) return;
    const int lane = threadIdx.x & 31;
    const int c = lane * 4;

    // self-loop contribution
    float4 acc = *(const float4*)(g_y + (size_t)w * HDIM + c);

    int e   = g_rowptr[w];
    int end = g_rowptr[w + 1];
    for (; e + 4 <= end; e += 4) {
        int c0 = g_col[e + 0], c1 = g_col[e + 1];
        int c2 = g_col[e + 2], c3 = g_col[e + 3];
        float4 v0 = *(const float4*)(g_y + (size_t)c0 * HDIM + c);
        float4 v1 = *(const float4*)(g_y + (size_t)c1 * HDIM + c);
        float4 v2 = *(const float4*)(g_y + (size_t)c2 * HDIM + c);
        float4 v3 = *(const float4*)(g_y + (size_t)c3 * HDIM + c);
        acc.x += (v0.x + v1.x) + (v2.x + v3.x);
        acc.y += (v0.y + v1.y) + (v2.y + v3.y);
        acc.z += (v0.z + v1.z) + (v2.z + v3.z);
        acc.w += (v0.w + v1.w) + (v2.w + v3.w);
    }
    for (; e < end; e++) {
        int cc = g_col[e];
        float4 v = *(const float4*)(g_y + (size_t)cc * HDIM + c);
        acc.x += v.x; acc.y += v.y; acc.z += v.z; acc.w += v.w;
    }

    float dv = g_dinv[w];
    float4 r;
    r.x = acc.x * dv + bias[c + 0];
    r.y = acc.y * dv + bias[c + 1];
    r.z = acc.z * dv + bias[c + 2];
    r.w = acc.w * dv + bias[c + 3];

    if (do_bn) {
        float i0 = rsqrtf(bnv[c + 0] + BN_EPS_F);
        float i1 = rsqrtf(bnv[c + 1] + BN_EPS_F);
        float i2 = rsqrtf(bnv[c + 2] + BN_EPS_F);
        float i3 = rsqrtf(bnv[c + 3] + BN_EPS_F);
        r.x = fmaxf((r.x - bnm[c + 0]) * i0 * bng[c + 0] + bnb[c + 0], 0.f);
        r.y = fmaxf((r.y - bnm[c + 1]) * i1 * bng[c + 1] + bnb[c + 1], 0.f);
        r.z = fmaxf((r.z - bnm[c + 2]) * i2 * bng[c + 2] + bnb[c + 2], 0.f);
        r.w = fmaxf((r.w - bnm[c + 3]) * i3 * bng[c + 3] + bnb[c + 3], 0.f);
    }

    *(float4*)(g_h + (size_t)w * HDIM + c) = r;
}

// ---------------- pooling (batch is sorted), reads g_h ------------------------
__device__ __forceinline__ int lower_bound_idx(const void* b, int n, int key, int is64) {
    int lo = 0, hi = n;
    while (lo < hi) {
        int mid = (lo + hi) >> 1;
        int v = idx_at(b, mid, is64);
        if (v < key) lo = mid + 1; else hi = mid;
    }
    return lo;
}

__global__ void __launch_bounds__(256)
k_pool(const void* __restrict__ batch, int n)
{
    __shared__ float red[256];
    const int g = blockIdx.x;
    const int t = threadIdx.x;
    const int col  = t & 127;
    const int half = t >> 7;  // 0/1
    const int is64 = g_is64;

    int start = lower_bound_idx(batch, n, g, is64);
    int end   = lower_bound_idx(batch, n, g + 1, is64);

    float a0 = 0.f, a1 = 0.f, a2 = 0.f, a3 = 0.f;
    int r = start + half;
    for (; r + 6 < end; r += 8) {
        a0 += g_h[(size_t)r * HDIM + col];
        a1 += g_h[(size_t)(r + 2) * HDIM + col];
        a2 += g_h[(size_t)(r + 4) * HDIM + col];
        a3 += g_h[(size_t)(r + 6) * HDIM + col];
    }
    for (; r < end; r += 2) a0 += g_h[(size_t)r * HDIM + col];
    red[t] = (a0 + a1) + (a2 + a3);
    __syncthreads();
    if (half == 0) {
        float s = red[t] + red[t + 128];
        float cnt = (float)(end - start);
        g_pool[g * HDIM + col] = s / fmaxf(cnt, 1.f);
    }
}

// ---------------- classifier MLP: [64,128]->relu[64,64]->[64,16] --------------
__global__ void __launch_bounds__(256)
k_cls(const float* __restrict__ Wc1, const float* __restrict__ bc1,
      const float* __restrict__ Wc2, const float* __restrict__ bc2,
      float* __restrict__ out)
{
    __shared__ float z[64][65];
    const int t = threadIdx.x;
    // 256 threads = 64 graphs x 4 col-blocks of 16
    {
        int g  = t >> 2;
        int cb = (t & 3) * 16;
        float s[16];
        #pragma unroll
        for (int j = 0; j < 16; j++) s[j] = bc1[cb + j];
        for (int k = 0; k < HDIM; k++) {
            float a = g_pool[g * HDIM + k];
            #pragma unroll
            for (int j = 0; j < 16; j++)
                s[j] = fmaf(a, Wc1[k * 64 + cb + j], s[j]);
        }
        #pragma unroll
        for (int j = 0; j < 16; j++) z[g][cb + j] = fmaxf(s[j], 0.f);
    }
    __syncthreads();
    // 1024 outputs / 256 threads = 4 each
    #pragma unroll
    for (int rep = 0; rep < 4; rep++) {
        int idx = t + rep * 256;
        int g = idx >> 4, c = idx & 15;
        float s = bc2[c];
        #pragma unroll
        for (int k = 0; k < 64; k++)
            s = fmaf(z[g][k], Wc2[k * 16 + c], s);
        out[idx] = s;
    }
}

// ---------------- launch -------------------------------------------------------
extern "C" void kernel_launch(void* const* d_in, const int* in_sizes, int n_in,
                              void* d_out, int out_size)
{
    const float* x     = (const float*)d_in[0];
    const void*  ei    = d_in[1];
    const void*  batch = d_in[2];
    const float* W1  = (const float*)d_in[3];
    const float* b1  = (const float*)d_in[4];
    const float* W2  = (const float*)d_in[5];
    const float* b2  = (const float*)d_in[6];
    const float* W3  = (const float*)d_in[7];
    const float* b3  = (const float*)d_in[8];
    const float* bn1g = (const float*)d_in[9];
    const float* bn1b = (const float*)d_in[10];
    const float* bn1m = (const float*)d_in[11];
    const float* bn1v = (const float*)d_in[12];
    const float* bn2g = (const float*)d_in[13];
    const float* bn2b = (const float*)d_in[14];
    const float* bn2m = (const float*)d_in[15];
    const float* bn2v = (const float*)d_in[16];
    const float* Wc1 = (const float*)d_in[17];
    const float* bc1 = (const float*)d_in[18];
    const float* Wc2 = (const float*)d_in[19];
    const float* bc2 = (const float*)d_in[20];

    const int n = in_sizes[2];          // nodes (batch has N elements)
    const int e = in_sizes[1] / 2;      // edges (edge_index has 2E elements)
    const int K1 = in_sizes[0] / n;     // input feature dim (256)
    const int nb = (n + SCAN_BLK - 1) / SCAN_BLK;

    // dtype probe + CSR build
    k_zero_deg<<<(n + 255) / 256, 256>>>(n);
    {
        int nwords = in_sizes[1];                      // safe lower bound in 32-bit words
        if (nwords > 16384) nwords = 16384;
        k_probe<<<(nwords / 2 + 255) / 256, 256>>>((const unsigned*)ei, nwords);
    }
    k_hist<<<(e + 255) / 256, 256>>>(ei, e);
    k_scan1<<<nb, SCAN_BLK>>>(n);
    k_scan2<<<1, MAXNB>>>(nb, n);
    k_scan3<<<(n + 255) / 256, 256>>>(n);
    k_fill<<<(e + 255) / 256, 256>>>(ei, e);

    const int gblk = (n + 127) / 128;
    const int ablk = ((n * 32) + 255) / 256;

    // conv1 (+BN1+ReLU)
    k_gemm<0><<<gblk, 256>>>(x, W1, n, K1);
    k_aggr<<<ablk, 256>>>(b1, bn1g, bn1b, bn1m, bn1v, 1, n);
    // conv2 (+BN2+ReLU)
    k_gemm<1><<<gblk, 256>>>(x, W2, n, HDIM);
    k_aggr<<<ablk, 256>>>(b2, bn2g, bn2b, bn2m, bn2v, 1, n);
    // conv3 (no BN)
    k_gemm<1><<<gblk, 256>>>(x, W3, n, HDIM);
    k_aggr<<<ablk, 256>>>(b3, bn1g, bn1b, bn1m, bn1v, 0, n);

    // pool + classifier
    k_pool<<<NG, 256>>>(batch, n);
    k_cls<<<1, 256>>>(Wc1, bc1, Wc2, bc2, (float*)d_out);
}

// round 7
// speedup vs baseline: 1.2687x; 1.2687x over previous
#include <cuda_runtime.h>
#include <cuda_bf16.h>
#include <cstdint>
#include <cstddef>

#define NMAX 50000
#define EMAX 800000
#define HDIM 128
#define NG 64
#define BN_EPS_F 1e-5f
#define SCAN_BLK 1024
#define MAXNB 64   // ceil(NMAX/SCAN_BLK) = 49

// ---------------- scratch (static device globals; no runtime alloc) ----------
__device__ int   g_is64;               // 1 if int inputs are int64, 0 if int32
__device__ int   g_deg[NMAX];
__device__ int   g_incl[NMAX];         // block-local inclusive scan temp
__device__ int   g_bsum[MAXNB];
__device__ int   g_boff[MAXNB];
__device__ int   g_rowptr[NMAX + 1];
__device__ int   g_cursor[NMAX];
__device__ int   g_col[EMAX];
__device__ float g_dinv[NMAX];
__device__ __align__(16) float g_y[(size_t)NMAX * HDIM];
__device__ __align__(16) float g_h[(size_t)NMAX * HDIM];
__device__ __align__(16) float g_pool[NG * HDIM];

// dtype-dispatched integer load
__device__ __forceinline__ int idx_at(const void* p, long long i, int is64) {
    if (is64) return (int)((const long long*)p)[i];
    return ((const int*)p)[i];
}

// ---------------- helpers ------------------------------------------------------
__device__ __forceinline__ uint32_t smem_u32(const void* p) {
    uint32_t a;
    asm("{ .reg .u64 t; cvta.to.shared.u64 t, %1; cvt.u32.u64 %0, t; }"
        : "=r"(a) : "l"(p));
    return a;
}
__device__ __forceinline__ void ldm_x4(uint32_t addr, uint32_t* r) {
    asm volatile("ldmatrix.sync.aligned.m8n8.x4.shared.b16 {%0,%1,%2,%3}, [%4];"
                 : "=r"(r[0]), "=r"(r[1]), "=r"(r[2]), "=r"(r[3]) : "r"(addr));
}
__device__ __forceinline__ void mma_bf16(float* c, const uint32_t* a,
                                         uint32_t b0, uint32_t b1) {
    asm volatile(
        "mma.sync.aligned.m16n8k16.row.col.f32.bf16.bf16.f32 "
        "{%0,%1,%2,%3}, {%4,%5,%6,%7}, {%8,%9}, {%0,%1,%2,%3};"
        : "+f"(c[0]), "+f"(c[1]), "+f"(c[2]), "+f"(c[3])
        : "r"(a[0]), "r"(a[1]), "r"(a[2]), "r"(a[3]), "r"(b0), "r"(b1));
}
__device__ __forceinline__ void split2(float x0, float x1,
                                       uint32_t& h01, uint32_t& l01) {
    __nv_bfloat16 h0 = __float2bfloat16_rn(x0);
    __nv_bfloat16 h1 = __float2bfloat16_rn(x1);
    __nv_bfloat16 l0 = __float2bfloat16_rn(x0 - __bfloat162float(h0));
    __nv_bfloat16 l1 = __float2bfloat16_rn(x1 - __bfloat162float(h1));
    h01 = (uint32_t)__bfloat16_as_ushort(h0) |
          ((uint32_t)__bfloat16_as_ushort(h1) << 16);
    l01 = (uint32_t)__bfloat16_as_ushort(l0) |
          ((uint32_t)__bfloat16_as_ushort(l1) << 16);
}

// ---------------- dtype probe: odd 32-bit words all zero <=> int64 ----------
__global__ void k_probe(const unsigned* __restrict__ w, int nwords) {
    int i = blockIdx.x * blockDim.x + threadIdx.x;
    int odd = i * 2 + 1;
    if (odd < nwords && w[odd] != 0) g_is64 = 0;
}

__global__ void k_zero_deg(int n) {
    int i = blockIdx.x * blockDim.x + threadIdx.x;
    if (i == 0) g_is64 = 1;
    if (i < n) g_deg[i] = 0;
}

__global__ void k_hist(const void* __restrict__ ei, int e) {
    int i = blockIdx.x * blockDim.x + threadIdx.x;
    if (i < e) {
        int is64 = g_is64;
        int d = idx_at(ei, (long long)e + i, is64);   // dst row
        atomicAdd(&g_deg[d], 1);
    }
}

// -------- phase 1: block-local inclusive scan of g_deg -> g_incl, g_bsum -----
__global__ void __launch_bounds__(SCAN_BLK)
k_scan1(int n) {
    __shared__ int wsum[32];
    const int t = threadIdx.x, lane = t & 31, wid = t >> 5;
    const int i = blockIdx.x * SCAN_BLK + t;
    int v = (i < n) ? g_deg[i] : 0;
    int s = v;
    #pragma unroll
    for (int o = 1; o < 32; o <<= 1) {
        int u = __shfl_up_sync(0xffffffffu, s, o);
        if (lane >= o) s += u;
    }
    if (lane == 31) wsum[wid] = s;
    __syncthreads();
    if (wid == 0) {
        int ws = wsum[lane];
        int sc = ws;
        #pragma unroll
        for (int o = 1; o < 32; o <<= 1) {
            int u = __shfl_up_sync(0xffffffffu, sc, o);
            if (lane >= o) sc += u;
        }
        wsum[lane] = sc - ws;   // exclusive warp offset
    }
    __syncthreads();
    s += wsum[wid];
    if (i < n) g_incl[i] = s;
    if (t == SCAN_BLK - 1) g_bsum[blockIdx.x] = s;
}

// -------- phase 2: exclusive scan of block sums (nb <= 64), total -> rowptr[n]
__global__ void k_scan2(int nb, int n) {
    __shared__ int w0tot;
    const int t = threadIdx.x, lane = t & 31, wid = t >> 5;
    int v = (t < nb) ? g_bsum[t] : 0;
    int s = v;
    #pragma unroll
    for (int o = 1; o < 32; o <<= 1) {
        int u = __shfl_up_sync(0xffffffffu, s, o);
        if (lane >= o) s += u;
    }
    if (wid == 0 && lane == 31) w0tot = s;
    __syncthreads();
    int incl = s + (wid ? w0tot : 0);
    if (t < nb) g_boff[t] = incl - v;
    if (t == nb - 1) g_rowptr[n] = incl;
}

// -------- phase 3: finalize rowptr/cursor/dinv --------------------------------
__global__ void k_scan3(int n) {
    int i = blockIdx.x * blockDim.x + threadIdx.x;
    if (i < n) {
        int v = g_deg[i];
        int excl = g_incl[i] - v + g_boff[i / SCAN_BLK];
        g_rowptr[i] = excl;
        g_cursor[i] = excl;
        g_dinv[i]   = rsqrtf((float)(v + 1));  // +1 self-loop
    }
}

__global__ void k_fill(const void* __restrict__ ei, int e) {
    int i = blockIdx.x * blockDim.x + threadIdx.x;
    if (i < e) {
        int is64 = g_is64;
        int s = idx_at(ei, i, is64);
        int d = idx_at(ei, (long long)e + i, is64);
        int p = atomicAdd(&g_cursor[d], 1);
        g_col[p] = s;
    }
}

// ---------------- HMMA split-bf16 GEMM: g_y = rowscale(A,dinv) @ W ------------
// D = Ah*Wh + Al*Wh + Ah*Wl, each term bf16 mma.sync m16n8k16, fp32 acc.
// 256 threads = 8 warps (2 m x 4 n). CTA tile 128x128, k-chunk 16.
#define RS 24   // smem row stride in bf16 elements (48B -> conflict-free ldmatrix)
template <int SRC>
__global__ void __launch_bounds__(256, 1)
k_gemm_mma(const float* __restrict__ Aarg, const float* __restrict__ W,
           int M, int K)
{
    __shared__ __align__(16) __nv_bfloat16 AH[128][RS];
    __shared__ __align__(16) __nv_bfloat16 AL[128][RS];
    __shared__ __align__(16) __nv_bfloat16 BH[128][RS];
    __shared__ __align__(16) __nv_bfloat16 BL[128][RS];

    const int tid  = threadIdx.x;
    const int wid  = tid >> 5;
    const int lane = tid & 31;
    const int wm   = wid >> 2;      // 0..1  (m block of 64 rows)
    const int wn   = wid & 3;       // 0..3  (n block of 32 cols)
    const int row0 = blockIdx.x * 128;

    const float* A = (SRC == 0) ? Aarg : g_h;

    float acc[4][4][4];
    #pragma unroll
    for (int a = 0; a < 4; a++)
        #pragma unroll
        for (int b = 0; b < 4; b++)
            #pragma unroll
            for (int c = 0; c < 4; c++) acc[a][b][c] = 0.f;

    // conversion mappings
    const int a_row = tid >> 1;          // 0..127
    const int a_q   = tid & 1;           // col half (8 floats)
    const int b_n   = tid & 127;         // output col
    const int b_q   = tid >> 7;          // k half

    float dvr = 0.f;
    if (row0 + a_row < M) dvr = g_dinv[row0 + a_row];

    // ldmatrix source addresses (fixed per thread)
    const uint32_t ah_base = smem_u32(&AH[0][0]);
    const uint32_t al_base = smem_u32(&AL[0][0]);
    const uint32_t bh_base = smem_u32(&BH[0][0]);
    const uint32_t bl_base = smem_u32(&BL[0][0]);
    const int am_row  = wm * 64 + (lane & 15);
    const int am_colb = ((lane >> 4) & 1) * 16;
    const int bn_row  = wn * 32 + (lane & 7) + ((lane >> 4) & 1) * 8;
    const int bn_colb = (lane & 8) * 2;

    for (int k0 = 0; k0 < K; k0 += 16) {
        // ---- convert A rows (each thread: 8 floats = 2 float4) ----
        {
            int row = row0 + a_row;
            float4 v0 = make_float4(0.f, 0.f, 0.f, 0.f);
            float4 v1 = v0;
            if (row < M) {
                const float* src = A + (size_t)row * K + k0 + a_q * 8;
                v0 = *(const float4*)src;
                v1 = *(const float4*)(src + 4);
            }
            uint32_t h01, l01, h23, l23, h45, l45, h67, l67;
            split2(v0.x * dvr, v0.y * dvr, h01, l01);
            split2(v0.z * dvr, v0.w * dvr, h23, l23);
            split2(v1.x * dvr, v1.y * dvr, h45, l45);
            split2(v1.z * dvr, v1.w * dvr, h67, l67);
            uint2* dh = (uint2*)&AH[a_row][a_q * 8];
            uint2* dl = (uint2*)&AL[a_row][a_q * 8];
            dh[0] = make_uint2(h01, h23); dh[1] = make_uint2(h45, h67);
            dl[0] = make_uint2(l01, l23); dl[1] = make_uint2(l45, l67);
        }
        // ---- convert W chunk transposed: BH/BL[n][k] = split(W[k0+k][n]) ----
        {
            float w[8];
            #pragma unroll
            for (int i = 0; i < 8; i++)
                w[i] = W[(size_t)(k0 + b_q * 8 + i) * HDIM + b_n];
            uint32_t h01, l01, h23, l23, h45, l45, h67, l67;
            split2(w[0], w[1], h01, l01);
            split2(w[2], w[3], h23, l23);
            split2(w[4], w[5], h45, l45);
            split2(w[6], w[7], h67, l67);
            uint2* dh = (uint2*)&BH[b_n][b_q * 8];
            uint2* dl = (uint2*)&BL[b_n][b_q * 8];
            dh[0] = make_uint2(h01, h23); dh[1] = make_uint2(h45, h67);
            dl[0] = make_uint2(l01, l23); dl[1] = make_uint2(l45, l67);
        }
        __syncthreads();

        // ---- load fragments ----
        uint32_t aH[4][4], aL[4][4], bHf[2][4], bLf[2][4];
        #pragma unroll
        for (int mt = 0; mt < 4; mt++) {
            uint32_t off = (uint32_t)((am_row + mt * 16) * (RS * 2) + am_colb);
            ldm_x4(ah_base + off, aH[mt]);
            ldm_x4(al_base + off, aL[mt]);
        }
        #pragma unroll
        for (int np = 0; np < 2; np++) {
            uint32_t off = (uint32_t)((bn_row + np * 16) * (RS * 2) + bn_colb);
            ldm_x4(bh_base + off, bHf[np]);
            ldm_x4(bl_base + off, bLf[np]);
        }

        // ---- 3 segments x 16 mma ----
        #pragma unroll
        for (int mt = 0; mt < 4; mt++)
            #pragma unroll
            for (int nt = 0; nt < 4; nt++) {
                uint32_t b0 = bHf[nt >> 1][(nt & 1) * 2];
                uint32_t b1 = bHf[nt >> 1][(nt & 1) * 2 + 1];
                mma_bf16(acc[mt][nt], aH[mt], b0, b1);
                mma_bf16(acc[mt][nt], aL[mt], b0, b1);
                uint32_t c0 = bLf[nt >> 1][(nt & 1) * 2];
                uint32_t c1 = bLf[nt >> 1][(nt & 1) * 2 + 1];
                mma_bf16(acc[mt][nt], aH[mt], c0, c1);
            }
        __syncthreads();
    }

    // ---- epilogue: fragment -> g_y ----
    const int rbase = row0 + wm * 64 + (lane >> 2);
    const int cbase = wn * 32 + (lane & 3) * 2;
    #pragma unroll
    for (int mt = 0; mt < 4; mt++)
        #pragma unroll
        for (int nt = 0; nt < 4; nt++) {
            int r = rbase + mt * 16;
            int c = cbase + nt * 8;
            if (r < M)
                *(float2*)(g_y + (size_t)r * HDIM + c) =
                    make_float2(acc[mt][nt][0], acc[mt][nt][1]);
            if (r + 8 < M)
                *(float2*)(g_y + (size_t)(r + 8) * HDIM + c) =
                    make_float2(acc[mt][nt][2], acc[mt][nt][3]);
        }
}

// -------- aggregation (pull / CSR): g_h = BN/ReLU(dinv*segsum(g_y) + b) ------
__global__ void __launch_bounds__(256)
k_aggr(const float* __restrict__ bias,
       const float* __restrict__ bng, const float* __restrict__ bnb,
       const float* __restrict__ bnm, const float* __restrict__ bnv,
       int do_bn, int n)
{
    int w = (blockIdx.x * blockDim.x + threadIdx.x) >> 5;
    if (w >= n) return;
    const int lane = threadIdx.x & 31;
    const int c = lane * 4;

    // self-loop contribution
    float4 acc = *(const float4*)(g_y + (size_t)w * HDIM + c);

    int e   = g_rowptr[w];
    int end = g_rowptr[w + 1];
    for (; e + 4 <= end; e += 4) {
        int c0 = g_col[e + 0], c1 = g_col[e + 1];
        int c2 = g_col[e + 2], c3 = g_col[e + 3];
        float4 v0 = *(const float4*)(g_y + (size_t)c0 * HDIM + c);
        float4 v1 = *(const float4*)(g_y + (size_t)c1 * HDIM + c);
        float4 v2 = *(const float4*)(g_y + (size_t)c2 * HDIM + c);
        float4 v3 = *(const float4*)(g_y + (size_t)c3 * HDIM + c);
        acc.x += (v0.x + v1.x) + (v2.x + v3.x);
        acc.y += (v0.y + v1.y) + (v2.y + v3.y);
        acc.z += (v0.z + v1.z) + (v2.z + v3.z);
        acc.w += (v0.w + v1.w) + (v2.w + v3.w);
    }
    for (; e < end; e++) {
        int cc = g_col[e];
        float4 v = *(const float4*)(g_y + (size_t)cc * HDIM + c);
        acc.x += v.x; acc.y += v.y; acc.z += v.z; acc.w += v.w;
    }

    float dv = g_dinv[w];
    float4 r;
    r.x = acc.x * dv + bias[c + 0];
    r.y = acc.y * dv + bias[c + 1];
    r.z = acc.z * dv + bias[c + 2];
    r.w = acc.w * dv + bias[c + 3];

    if (do_bn) {
        float i0 = rsqrtf(bnv[c + 0] + BN_EPS_F);
        float i1 = rsqrtf(bnv[c + 1] + BN_EPS_F);
        float i2 = rsqrtf(bnv[c + 2] + BN_EPS_F);
        float i3 = rsqrtf(bnv[c + 3] + BN_EPS_F);
        r.x = fmaxf((r.x - bnm[c + 0]) * i0 * bng[c + 0] + bnb[c + 0], 0.f);
        r.y = fmaxf((r.y - bnm[c + 1]) * i1 * bng[c + 1] + bnb[c + 1], 0.f);
        r.z = fmaxf((r.z - bnm[c + 2]) * i2 * bng[c + 2] + bnb[c + 2], 0.f);
        r.w = fmaxf((r.w - bnm[c + 3]) * i3 * bng[c + 3] + bnb[c + 3], 0.f);
    }

    *(float4*)(g_h + (size_t)w * HDIM + c) = r;
}

// ---------------- pooling (batch is sorted), reads g_h ------------------------
__device__ __forceinline__ int lower_bound_idx(const void* b, int n, int key, int is64) {
    int lo = 0, hi = n;
    while (lo < hi) {
        int mid = (lo + hi) >> 1;
        int v = idx_at(b, mid, is64);
        if (v < key) lo = mid + 1; else hi = mid;
    }
    return lo;
}

__global__ void __launch_bounds__(256)
k_pool(const void* __restrict__ batch, int n)
{
    __shared__ float red[256];
    const int g = blockIdx.x;
    const int t = threadIdx.x;
    const int col  = t & 127;
    const int half = t >> 7;  // 0/1
    const int is64 = g_is64;

    int start = lower_bound_idx(batch, n, g, is64);
    int end   = lower_bound_idx(batch, n, g + 1, is64);

    float a0 = 0.f, a1 = 0.f, a2 = 0.f, a3 = 0.f;
    int r = start + half;
    for (; r + 6 < end; r += 8) {
        a0 += g_h[(size_t)r * HDIM + col];
        a1 += g_h[(size_t)(r + 2) * HDIM + col];
        a2 += g_h[(size_t)(r + 4) * HDIM + col];
        a3 += g_h[(size_t)(r + 6) * HDIM + col];
    }
    for (; r < end; r += 2) a0 += g_h[(size_t)r * HDIM + col];
    red[t] = (a0 + a1) + (a2 + a3);
    __syncthreads();
    if (half == 0) {
        float s = red[t] + red[t + 128];
        float cnt = (float)(end - start);
        g_pool[g * HDIM + col] = s / fmaxf(cnt, 1.f);
    }
}

// ---------------- classifier MLP: [64,128]->relu[64,64]->[64,16] --------------
__global__ void __launch_bounds__(256)
k_cls(const float* __restrict__ Wc1, const float* __restrict__ bc1,
      const float* __restrict__ Wc2, const float* __restrict__ bc2,
      float* __restrict__ out)
{
    __shared__ float z[64][65];
    const int t = threadIdx.x;
    // 256 threads = 64 graphs x 4 col-blocks of 16
    {
        int g  = t >> 2;
        int cb = (t & 3) * 16;
        float s[16];
        #pragma unroll
        for (int j = 0; j < 16; j++) s[j] = bc1[cb + j];
        for (int k = 0; k < HDIM; k++) {
            float a = g_pool[g * HDIM + k];
            #pragma unroll
            for (int j = 0; j < 16; j++)
                s[j] = fmaf(a, Wc1[k * 64 + cb + j], s[j]);
        }
        #pragma unroll
        for (int j = 0; j < 16; j++) z[g][cb + j] = fmaxf(s[j], 0.f);
    }
    __syncthreads();
    // 1024 outputs / 256 threads = 4 each
    #pragma unroll
    for (int rep = 0; rep < 4; rep++) {
        int idx = t + rep * 256;
        int g = idx >> 4, c = idx & 15;
        float s = bc2[c];
        #pragma unroll
        for (int k = 0; k < 64; k++)
            s = fmaf(z[g][k], Wc2[k * 16 + c], s);
        out[idx] = s;
    }
}

// ---------------- launch -------------------------------------------------------
extern "C" void kernel_launch(void* const* d_in, const int* in_sizes, int n_in,
                              void* d_out, int out_size)
{
    const float* x     = (const float*)d_in[0];
    const void*  ei    = d_in[1];
    const void*  batch = d_in[2];
    const float* W1  = (const float*)d_in[3];
    const float* b1  = (const float*)d_in[4];
    const float* W2  = (const float*)d_in[5];
    const float* b2  = (const float*)d_in[6];
    const float* W3  = (const float*)d_in[7];
    const float* b3  = (const float*)d_in[8];
    const float* bn1g = (const float*)d_in[9];
    const float* bn1b = (const float*)d_in[10];
    const float* bn1m = (const float*)d_in[11];
    const float* bn1v = (const float*)d_in[12];
    const float* bn2g = (const float*)d_in[13];
    const float* bn2b = (const float*)d_in[14];
    const float* bn2m = (const float*)d_in[15];
    const float* bn2v = (const float*)d_in[16];
    const float* Wc1 = (const float*)d_in[17];
    const float* bc1 = (const float*)d_in[18];
    const float* Wc2 = (const float*)d_in[19];
    const float* bc2 = (const float*)d_in[20];

    const int n = in_sizes[2];          // nodes (batch has N elements)
    const int e = in_sizes[1] / 2;      // edges (edge_index has 2E elements)
    const int K1 = in_sizes[0] / n;     // input feature dim (256)
    const int nb = (n + SCAN_BLK - 1) / SCAN_BLK;

    // dtype probe + CSR build
    k_zero_deg<<<(n + 255) / 256, 256>>>(n);
    {
        int nwords = in_sizes[1];                      // safe lower bound in 32-bit words
        if (nwords > 16384) nwords = 16384;
        k_probe<<<(nwords / 2 + 255) / 256, 256>>>((const unsigned*)ei, nwords);
    }
    k_hist<<<(e + 255) / 256, 256>>>(ei, e);
    k_scan1<<<nb, SCAN_BLK>>>(n);
    k_scan2<<<1, MAXNB>>>(nb, n);
    k_scan3<<<(n + 255) / 256, 256>>>(n);
    k_fill<<<(e + 255) / 256, 256>>>(ei, e);

    const int gblk = (n + 127) / 128;
    const int ablk = ((n * 32) + 255) / 256;

    // conv1 (+BN1+ReLU)
    k_gemm_mma<0><<<gblk, 256>>>(x, W1, n, K1);
    k_aggr<<<ablk, 256>>>(b1, bn1g, bn1b, bn1m, bn1v, 1, n);
    // conv2 (+BN2+ReLU)
    k_gemm_mma<1><<<gblk, 256>>>(x, W2, n, HDIM);
    k_aggr<<<ablk, 256>>>(b2, bn2g, bn2b, bn2m, bn2v, 1, n);
    // conv3 (no BN)
    k_gemm_mma<1><<<gblk, 256>>>(x, W3, n, HDIM);
    k_aggr<<<ablk, 256>>>(b3, bn1g, bn1b, bn1m, bn1v, 0, n);

    // pool + classifier
    k_pool<<<NG, 256>>>(batch, n);
    k_cls<<<1, 256>>>(Wc1, bc1, Wc2, bc2, (float*)d_out);
}